// round 6
// baseline (speedup 1.0000x reference)
#include <cuda_runtime.h>
#include <math.h>

#define NG    2048
#define W     128
#define H     128
#define EPSV  1e-4f
#define NEARV 0.3f
#define TW    16          // tile width (px)
#define TH    8           // tile height (px)
#define PPT   (TW*TH)     // 128 pixels per tile
#define NTX   (W/TW)      // 8
#define NTY   (H/TH)      // 16
#define NSUB  8           // depth chunks per render block
#define BT    (NSUB*PPT)  // 1024 threads
#define TAU   18.2f       // cull threshold on folded exponent

// ---------------- device scratch ----------------
// unsorted (written by prep)
__device__ float4 d_ga [NG];   // u, v, A, B
__device__ float4 d_gb [NG];   // C, L, r, g
__device__ float4 d_cu [NG];   // u, v, hx, hy
__device__ float  d_bb [NG];   // b
__device__ float  d_key[NG];   // depth key
// sorted (written by sortgather)
__device__ float4 d_sga [NG];
__device__ float4 d_sgb [NG];
__device__ float4 d_scu [NG];
__device__ float  d_sbb [NG];

__device__ __forceinline__ float sigmoidf_(float x) {
    return 1.0f / (1.0f + expf(-x));
}

// ---------------- 1) per-gaussian preprocessing ----------------
__global__ void prep_kernel(const float* __restrict__ pos,
                            const float* __restrict__ rgb,
                            const float* __restrict__ opa,
                            const float* __restrict__ quat,
                            const float* __restrict__ scale,
                            const float* __restrict__ rot,
                            const float* __restrict__ tran)
{
    int n = blockIdx.x * blockDim.x + threadIdx.x;
    if (n >= NG) return;

    float Rw[9];
#pragma unroll
    for (int i = 0; i < 9; i++) Rw[i] = __ldg(&rot[i]);
    float t0 = __ldg(&tran[0]), t1 = __ldg(&tran[1]), t2 = __ldg(&tran[2]);

    float p0 = pos[n*3+0], p1 = pos[n*3+1], p2 = pos[n*3+2];
    float x = Rw[0]*p0 + Rw[1]*p1 + Rw[2]*p2 + t0;
    float y = Rw[3]*p0 + Rw[4]*p1 + Rw[5]*p2 + t1;
    float z = Rw[6]*p0 + Rw[7]*p1 + Rw[8]*p2 + t2;

    float r = sqrtf(x*x + y*y + z*z);
    float iz  = 1.0f / z;
    float u = x * iz, v = y * iz;
    float iz2 = iz * iz;

    float M00 = iz*Rw[0] - x*iz2*Rw[6];
    float M01 = iz*Rw[1] - x*iz2*Rw[7];
    float M02 = iz*Rw[2] - x*iz2*Rw[8];
    float M10 = iz*Rw[3] - y*iz2*Rw[6];
    float M11 = iz*Rw[4] - y*iz2*Rw[7];
    float M12 = iz*Rw[5] - y*iz2*Rw[8];

    float qw = quat[n*4+0], qx = quat[n*4+1], qy = quat[n*4+2], qz = quat[n*4+3];
    float qn = rsqrtf(qw*qw + qx*qx + qy*qy + qz*qz);
    qw *= qn; qx *= qn; qy *= qn; qz *= qn;
    float R00 = 1.0f - 2.0f*(qy*qy + qz*qz);
    float R01 = 2.0f*(qx*qy - qw*qz);
    float R02 = 2.0f*(qx*qz + qw*qy);
    float R10 = 2.0f*(qx*qy + qw*qz);
    float R11 = 1.0f - 2.0f*(qx*qx + qz*qz);
    float R12 = 2.0f*(qy*qz - qw*qx);
    float R20 = 2.0f*(qx*qz - qw*qy);
    float R21 = 2.0f*(qy*qz + qw*qx);
    float R22 = 1.0f - 2.0f*(qx*qx + qy*qy);

    float s0 = fabsf(scale[n*3+0]) + 1e-4f;
    float s1 = fabsf(scale[n*3+1]) + 1e-4f;
    float s2 = fabsf(scale[n*3+2]) + 1e-4f;
    float q0 = s0*s0, q1 = s1*s1, q2 = s2*s2;

    float c00 = R00*R00*q0 + R01*R01*q1 + R02*R02*q2;
    float c01 = R00*R10*q0 + R01*R11*q1 + R02*R12*q2;
    float c02 = R00*R20*q0 + R01*R21*q1 + R02*R22*q2;
    float c11 = R10*R10*q0 + R11*R11*q1 + R12*R12*q2;
    float c12 = R10*R20*q0 + R11*R21*q1 + R12*R22*q2;
    float c22 = R20*R20*q0 + R21*R21*q1 + R22*R22*q2;

    float v00 = c00*M00 + c01*M01 + c02*M02;
    float v01 = c01*M00 + c11*M01 + c12*M02;
    float v02 = c02*M00 + c12*M01 + c22*M02;
    float v10 = c00*M10 + c01*M11 + c02*M12;
    float v11 = c01*M10 + c11*M11 + c12*M12;
    float v12 = c02*M10 + c12*M11 + c22*M12;

    float a  = M00*v00 + M01*v01 + M02*v02 + EPSV;   // Sigma_xx
    float b  = M00*v10 + M01*v11 + M02*v12;
    float cc = M10*v10 + M11*v11 + M12*v12 + EPSV;   // Sigma_yy

    float det  = a*cc - b*b;
    float idet = 1.0f / det;
    float A = -0.5f * cc * idet;
    float B =  b * idet;
    float C = -0.5f * a  * idet;

    float opa_s = sigmoidf_(opa[n]);
    float L = (z > NEARV) ? logf(opa_s) : -1e30f;

    // exact AABB of the tau-level ellipse: half-widths sqrt(2*tau*Sigma)
    float tau = TAU + L;
    float hx, hy;
    if (tau > 0.0f) {
        hx = sqrtf(2.0f * tau * a);
        hy = sqrtf(2.0f * tau * cc);
    } else {
        hx = -1e30f; hy = -1e30f;   // empty -> always culled
    }

    float cr = sigmoidf_(rgb[n*3+0]);
    float cg = sigmoidf_(rgb[n*3+1]);
    float cb = sigmoidf_(rgb[n*3+2]);

    d_cu [n] = make_float4(u, v, hx, hy);
    d_ga [n] = make_float4(u, v, A, B);
    d_gb [n] = make_float4(C, L, cr, cg);
    d_bb [n] = cb;
    d_key[n] = r;
}

// ---------------- 2) global stable rank-sort + gather ----------------
// grid 128 x 128 threads; warp per gaussian-batch: each warp ranks 4 gaussians.
__global__ void __launch_bounds__(128) sortgather_kernel()
{
    __shared__ float sk[NG];
    int t = threadIdx.x;
    for (int i = t; i < NG; i += 128) sk[i] = __ldg(&d_key[i]);
    __syncthreads();

    int wid = t >> 5, lane = t & 31;
#pragma unroll
    for (int ii = 0; ii < 4; ii++) {
        int i = (blockIdx.x * 4 + wid) * 4 + ii;   // original index
        float ki = sk[i];
        int c = 0;
#pragma unroll 8
        for (int j = lane; j < NG; j += 32) {
            float kj = sk[j];
            c += (int)((kj < ki) | ((kj == ki) & (j < i)));   // stable ties
        }
#pragma unroll
        for (int o = 16; o; o >>= 1) c += __shfl_xor_sync(0xFFFFFFFFu, c, o);
        // all lanes have rank c; lanes 0..3 scatter payloads
        if      (lane == 0) d_sga[c] = d_ga[i];
        else if (lane == 1) d_sgb[c] = d_gb[i];
        else if (lane == 2) d_scu[c] = d_cu[i];
        else if (lane == 3) d_sbb[c] = d_bb[i];
    }
}

// ---------------- 3) per-tile compact + chunked composite ----------------
extern __shared__ char smx[];

__global__ void __launch_bounds__(BT, 1) render_kernel(float* __restrict__ out)
{
    float4* sga  = (float4*)(smx);                 // 32KB sorted-survivor u,v,A,B
    float4* sgb  = (float4*)(smx + 32768);         // 32KB C,L,r,g
    float4* part = (float4*)(smx + 65536);         // 16KB [NSUB][PPT]
    float*  sbb  = (float* )(smx + 81920);         //  8KB b
    int*    sidx = (int*  )(smx + 90112);          //  8KB survivor ids (sorted order)
    __shared__ int warpcnt[32];

    int t    = threadIdx.x;
    int wid  = t >> 5, lane = t & 31;
    int tx   = blockIdx.x, ty = blockIdx.y;

    const float xmin = (tx*TW        - 63.5f) * (1.0f/128.0f);
    const float xmax = (tx*TW + TW-1 - 63.5f) * (1.0f/128.0f);
    const float ymin = (ty*TH        - 63.5f) * (1.0f/128.0f);
    const float ymax = (ty*TH + TH-1 - 63.5f) * (1.0f/128.0f);

    // ---- order-preserving compaction of sorted list ----
    int base = 0;
#pragma unroll
    for (int p = 0; p < NG/BT; p++) {
        int i = p*BT + t;
        float4 cv = __ldg(&d_scu[i]);
        bool keep = (cv.x - cv.z <= xmax) && (cv.x + cv.z >= xmin) &&
                    (cv.y - cv.w <= ymax) && (cv.y + cv.w >= ymin);
        unsigned m = __ballot_sync(0xFFFFFFFFu, keep);
        int wofs = __popc(m & ((1u << lane) - 1u));
        if (lane == 0) warpcnt[wid] = __popc(m);
        __syncthreads();
        if (t < 32) {
            int v = warpcnt[t];
#pragma unroll
            for (int o = 1; o < 32; o <<= 1) {
                int u2 = __shfl_up_sync(0xFFFFFFFFu, v, o);
                if (lane >= o) v += u2;
            }
            warpcnt[t] = v;     // inclusive scan
        }
        __syncthreads();
        int wbase = base + (wid ? warpcnt[wid-1] : 0);
        if (keep) sidx[wbase + wofs] = i;
        base += warpcnt[31];
        __syncthreads();
    }
    int N = base;

    // ---- stage survivors into smem ----
    for (int k = t; k < N; k += BT) {
        int g = sidx[k];
        sga[k] = __ldg(&d_sga[g]);
        sgb[k] = __ldg(&d_sgb[g]);
        sbb[k] = __ldg(&d_sbb[g]);
    }
    __syncthreads();

    // ---- chunked branch-free composite ----
    int sub = t >> 7;            // 0..7 depth chunk
    int pix = t & (PPT-1);       // 0..127 pixel in tile
    int x = tx*TW + (pix & (TW-1));
    int y = ty*TH + (pix >> 4);
    float px = (x - 63.5f) * (1.0f/128.0f);
    float py = (y - 63.5f) * (1.0f/128.0f);

    int Nc = (N + NSUB - 1) / NSUB;
    int k0 = sub * Nc;
    int k1 = k0 + Nc; if (k1 > N) k1 = N;

    float T = 1.0f, cr = 0.0f, cg = 0.0f, cb = 0.0f;
#pragma unroll 4
    for (int k = k0; k < k1; k++) {
        float4 ga = sga[k];
        float4 gb = sgb[k];
        float dx = px - ga.x;
        float dy = py - ga.y;
        float pw = fmaf(fmaf(ga.z, dx, ga.w * dy), dx, fmaf(gb.x * dy, dy, gb.y));
        float al = fminf(__expf(pw), 0.99f);
        float wg = T * al;
        cr = fmaf(wg, gb.z, cr);
        cg = fmaf(wg, gb.w, cg);
        cb = fmaf(wg, sbb[k], cb);
        T -= wg;
    }
    part[sub * PPT + pix] = make_float4(cr, cg, cb, T);
    __syncthreads();

    // ---- exact recombination ----
    if (t < PPT) {
        float P = 1.0f, r = 0.0f, g = 0.0f, b = 0.0f;
#pragma unroll
        for (int s = 0; s < NSUB; s++) {
            float4 q = part[s * PPT + t];
            r = fmaf(P, q.x, r);
            g = fmaf(P, q.y, g);
            b = fmaf(P, q.z, b);
            P *= q.w;
        }
        int xx = tx*TW + (t & (TW-1));
        int yy = ty*TH + (t >> 4);
        int o = (yy * W + xx) * 3;
        out[o + 0] = r;
        out[o + 1] = g;
        out[o + 2] = b;
    }
}

#define RENDER_SMEM (98304)

extern "C" void kernel_launch(void* const* d_in, const int* in_sizes, int n_in,
                              void* d_out, int out_size)
{
    const float* pos   = (const float*)d_in[0];
    const float* rgb   = (const float*)d_in[1];
    const float* opa   = (const float*)d_in[2];
    const float* quat  = (const float*)d_in[3];
    const float* scale = (const float*)d_in[4];
    const float* rot   = (const float*)d_in[5];
    const float* tran  = (const float*)d_in[6];
    float* out = (float*)d_out;

    static int smem_set = 0;
    if (!smem_set) {
        cudaFuncSetAttribute(render_kernel,
                             cudaFuncAttributeMaxDynamicSharedMemorySize,
                             RENDER_SMEM);
        smem_set = 1;
    }

    prep_kernel<<<NG/256, 256>>>(pos, rgb, opa, quat, scale, rot, tran);
    sortgather_kernel<<<128, 128>>>();
    render_kernel<<<dim3(NTX, NTY), BT, RENDER_SMEM>>>(out);
}

// round 8
// speedup vs baseline: 1.3843x; 1.3843x over previous
#include <cuda_runtime.h>
#include <math.h>

#define NG    2048
#define W     128
#define H     128
#define EPSV  1e-4f
#define NEARV 0.3f
#define TW    16          // tile width (px)
#define TH    8           // tile height (px)
#define PPT   (TW*TH)     // 128 pixels per tile
#define NTX   (W/TW)      // 8
#define NTY   (H/TH)      // 16
#define NSUB  8           // depth chunks per block
#define BT    (NSUB*PPT)  // 1024 threads
#define TAU   18.2f       // cull threshold on folded exponent

// smem layout (bytes)
#define O_SM0   0                    // float4[NG]  u,v,A,B        32KB
#define O_SM1   (O_SM0 + 32768)      // float4[NG]  C,L,r,g        32KB
#define O_SCUL  (O_SM1 + 32768)      // float4[NG]  u,v,hx,hy      32KB
#define O_PART  (O_SCUL + 32768)     // float4[NSUB*PPT] 16KB (aliased as skc pre-phase4)
#define O_SKEY  (O_PART + 16384)     // float[NG]                   8KB
#define O_SBB   (O_SKEY + 8192)      // float[NG]                   8KB
#define O_SIDX  (O_SBB + 8192)       // int[NG] survivors (orig order) 8KB
#define O_SORD  (O_SIDX + 8192)      // int[NG] survivors (depth order) 8KB
#define SMEM_TOTAL (O_SORD + 8192)   // 147456 B

extern __shared__ char smx[];

__device__ __forceinline__ float sigmoidf_(float x) {
    return 1.0f / (1.0f + expf(-x));
}

__global__ void __launch_bounds__(BT, 1)
splat_kernel(const float* __restrict__ pos,
             const float* __restrict__ rgb,
             const float* __restrict__ opa,
             const float* __restrict__ quat,
             const float* __restrict__ scale,
             const float* __restrict__ rot,
             const float* __restrict__ tran,
             float* __restrict__ out)
{
    float4* sm0  = (float4*)(smx + O_SM0);
    float4* sm1  = (float4*)(smx + O_SM1);
    float4* scul = (float4*)(smx + O_SCUL);
    float4* part = (float4*)(smx + O_PART);
    float*  skc  = (float* )(smx + O_PART);   // alias: compact keys, dead before part written
    float*  skey = (float* )(smx + O_SKEY);
    float*  sbb  = (float* )(smx + O_SBB);
    int*    sidx = (int*  )(smx + O_SIDX);
    int*    sord = (int*  )(smx + O_SORD);
    __shared__ int warpcnt[32];

    const int t    = threadIdx.x;
    const int wid  = t >> 5, lane = t & 31;
    const int tx   = blockIdx.x, ty = blockIdx.y;

    // ---------------- phase 1: in-block prep of all gaussians ----------------
    float Rw[9];
#pragma unroll
    for (int i = 0; i < 9; i++) Rw[i] = __ldg(&rot[i]);
    const float t0 = __ldg(&tran[0]), t1 = __ldg(&tran[1]), t2 = __ldg(&tran[2]);

#pragma unroll
    for (int n = t; n < NG; n += BT) {
        float p0 = __ldg(&pos[n*3+0]), p1 = __ldg(&pos[n*3+1]), p2 = __ldg(&pos[n*3+2]);
        float x = Rw[0]*p0 + Rw[1]*p1 + Rw[2]*p2 + t0;
        float y = Rw[3]*p0 + Rw[4]*p1 + Rw[5]*p2 + t1;
        float z = Rw[6]*p0 + Rw[7]*p1 + Rw[8]*p2 + t2;

        float r = sqrtf(x*x + y*y + z*z);
        float iz  = 1.0f / z;
        float u = x * iz, v = y * iz;
        float iz2 = iz * iz;

        float M00 = iz*Rw[0] - x*iz2*Rw[6];
        float M01 = iz*Rw[1] - x*iz2*Rw[7];
        float M02 = iz*Rw[2] - x*iz2*Rw[8];
        float M10 = iz*Rw[3] - y*iz2*Rw[6];
        float M11 = iz*Rw[4] - y*iz2*Rw[7];
        float M12 = iz*Rw[5] - y*iz2*Rw[8];

        float4 q4 = __ldg((const float4*)(quat + n*4));
        float qw = q4.x, qx = q4.y, qy = q4.z, qz = q4.w;
        float qn = rsqrtf(qw*qw + qx*qx + qy*qy + qz*qz);
        qw *= qn; qx *= qn; qy *= qn; qz *= qn;
        float R00 = 1.0f - 2.0f*(qy*qy + qz*qz);
        float R01 = 2.0f*(qx*qy - qw*qz);
        float R02 = 2.0f*(qx*qz + qw*qy);
        float R10 = 2.0f*(qx*qy + qw*qz);
        float R11 = 1.0f - 2.0f*(qx*qx + qz*qz);
        float R12 = 2.0f*(qy*qz - qw*qx);
        float R20 = 2.0f*(qx*qz - qw*qy);
        float R21 = 2.0f*(qy*qz + qw*qx);
        float R22 = 1.0f - 2.0f*(qx*qx + qy*qy);

        float s0 = fabsf(__ldg(&scale[n*3+0])) + 1e-4f;
        float s1 = fabsf(__ldg(&scale[n*3+1])) + 1e-4f;
        float s2 = fabsf(__ldg(&scale[n*3+2])) + 1e-4f;
        float q0 = s0*s0, q1 = s1*s1, q2 = s2*s2;

        float c00 = R00*R00*q0 + R01*R01*q1 + R02*R02*q2;
        float c01 = R00*R10*q0 + R01*R11*q1 + R02*R12*q2;
        float c02 = R00*R20*q0 + R01*R21*q1 + R02*R22*q2;
        float c11 = R10*R10*q0 + R11*R11*q1 + R12*R12*q2;
        float c12 = R10*R20*q0 + R11*R21*q1 + R12*R22*q2;
        float c22 = R20*R20*q0 + R21*R21*q1 + R22*R22*q2;

        float v00 = c00*M00 + c01*M01 + c02*M02;
        float v01 = c01*M00 + c11*M01 + c12*M02;
        float v02 = c02*M00 + c12*M01 + c22*M02;
        float v10 = c00*M10 + c01*M11 + c02*M12;
        float v11 = c01*M10 + c11*M11 + c12*M12;
        float v12 = c02*M10 + c12*M11 + c22*M12;

        float a  = M00*v00 + M01*v01 + M02*v02 + EPSV;   // Sigma_xx
        float b  = M00*v10 + M01*v11 + M02*v12;
        float cc = M10*v10 + M11*v11 + M12*v12 + EPSV;   // Sigma_yy

        float det  = a*cc - b*b;
        float idet = 1.0f / det;
        float A = -0.5f * cc * idet;
        float B =  b * idet;
        float C = -0.5f * a  * idet;

        float opa_s = sigmoidf_(__ldg(&opa[n]));
        float L = (z > NEARV) ? logf(opa_s) : -1e30f;

        float tau = TAU + L;
        float hx, hy;
        if (tau > 0.0f) {
            hx = sqrtf(2.0f * tau * a);
            hy = sqrtf(2.0f * tau * cc);
        } else {
            hx = -1e30f; hy = -1e30f;   // always culled
        }

        float cr = sigmoidf_(__ldg(&rgb[n*3+0]));
        float cg = sigmoidf_(__ldg(&rgb[n*3+1]));
        float cb = sigmoidf_(__ldg(&rgb[n*3+2]));

        scul[n] = make_float4(u, v, hx, hy);
        sm0 [n] = make_float4(u, v, A, B);
        sm1 [n] = make_float4(C, L, cr, cg);
        sbb [n] = cb;
        skey[n] = r;
    }
    __syncthreads();

    // ---------------- phase 2: order-preserving compaction vs tile AABB ----------------
    const float xmin = (tx*TW        - 63.5f) * (1.0f/128.0f);
    const float xmax = (tx*TW + TW-1 - 63.5f) * (1.0f/128.0f);
    const float ymin = (ty*TH        - 63.5f) * (1.0f/128.0f);
    const float ymax = (ty*TH + TH-1 - 63.5f) * (1.0f/128.0f);

    int base = 0;
#pragma unroll
    for (int p = 0; p < NG/BT; p++) {       // uniform trip count, all threads
        int i = p*BT + t;
        float4 cv = scul[i];
        bool keep = (cv.x - cv.z <= xmax) && (cv.x + cv.z >= xmin) &&
                    (cv.y - cv.w <= ymax) && (cv.y + cv.w >= ymin);
        unsigned m = __ballot_sync(0xFFFFFFFFu, keep);
        int wofs = __popc(m & ((1u << lane) - 1u));
        if (lane == 0) warpcnt[wid] = __popc(m);
        __syncthreads();
        if (t < 32) {                        // whole warp 0 active
            int v = warpcnt[t];
#pragma unroll
            for (int o = 1; o < 32; o <<= 1) {
                int u2 = __shfl_up_sync(0xFFFFFFFFu, v, o);
                if (lane >= o) v += u2;
            }
            warpcnt[t] = v;                  // inclusive scan
        }
        __syncthreads();
        int wbase = base + (wid ? warpcnt[wid-1] : 0);
        if (keep) sidx[wbase + wofs] = i;
        base += warpcnt[31];
        __syncthreads();
    }
    const int N = base;

    // compact survivor keys (skc aliases part; part not used yet)
    for (int i = t; i < N; i += BT) skc[i] = skey[sidx[i]];
    __syncthreads();

    // ---------------- phase 3: rank-sort survivors (no warp collectives) ----------------
    for (int i = t; i < N; i += BT) {
        float ki = skc[i];
        int c = 0;
        for (int j = 0; j < N; j++) {
            float kj = skc[j];
            c += (int)((kj < ki) | ((kj == ki) & (j < i)));   // stable ties
        }
        sord[c] = sidx[i];
    }
    __syncthreads();

    // ---------------- phase 4: chunked branch-free composite ----------------
    const int sub = t >> 7;            // depth chunk 0..7
    const int pix = t & (PPT-1);       // pixel 0..127
    const int x = tx*TW + (pix & (TW-1));
    const int y = ty*TH + (pix >> 4);
    const float px = (x - 63.5f) * (1.0f/128.0f);
    const float py = (y - 63.5f) * (1.0f/128.0f);

    const int Nc = (N + NSUB - 1) / NSUB;
    const int k0 = sub * Nc;
    int k1 = k0 + Nc; if (k1 > N) k1 = N;

    float T = 1.0f, cr = 0.0f, cg = 0.0f, cb = 0.0f;
#pragma unroll 4
    for (int k = k0; k < k1; k++) {
        int g = sord[k];
        float4 ga = sm0[g];
        float4 gb = sm1[g];
        float dx = px - ga.x;
        float dy = py - ga.y;
        float pw = fmaf(fmaf(ga.z, dx, ga.w * dy), dx, fmaf(gb.x * dy, dy, gb.y));
        float al = fminf(__expf(pw), 0.99f);
        float wg = T * al;
        cr = fmaf(wg, gb.z, cr);
        cg = fmaf(wg, gb.w, cg);
        cb = fmaf(wg, sbb[g], cb);
        T -= wg;
    }
    __syncthreads();   // skc (aliasing part) fully dead before part is written
    part[sub * PPT + pix] = make_float4(cr, cg, cb, T);
    __syncthreads();

    // ---------------- phase 5: exact recombination + store ----------------
    if (t < PPT) {
        float P = 1.0f, r = 0.0f, g = 0.0f, b = 0.0f;
#pragma unroll
        for (int s = 0; s < NSUB; s++) {
            float4 qq = part[s * PPT + t];
            r = fmaf(P, qq.x, r);
            g = fmaf(P, qq.y, g);
            b = fmaf(P, qq.z, b);
            P *= qq.w;
        }
        int xx = tx*TW + (t & (TW-1));
        int yy = ty*TH + (t >> 4);
        int o = (yy * W + xx) * 3;
        out[o + 0] = r;
        out[o + 1] = g;
        out[o + 2] = b;
    }
}

extern "C" void kernel_launch(void* const* d_in, const int* in_sizes, int n_in,
                              void* d_out, int out_size)
{
    const float* pos   = (const float*)d_in[0];
    const float* rgb   = (const float*)d_in[1];
    const float* opa   = (const float*)d_in[2];
    const float* quat  = (const float*)d_in[3];
    const float* scale = (const float*)d_in[4];
    const float* rot   = (const float*)d_in[5];
    const float* tran  = (const float*)d_in[6];
    float* out = (float*)d_out;

    static int smem_set = 0;
    if (!smem_set) {
        cudaFuncSetAttribute(splat_kernel,
                             cudaFuncAttributeMaxDynamicSharedMemorySize,
                             SMEM_TOTAL);
        smem_set = 1;
    }

    splat_kernel<<<dim3(NTX, NTY), BT, SMEM_TOTAL>>>(pos, rgb, opa, quat, scale,
                                                     rot, tran, out);
}